// round 14
// baseline (speedup 1.0000x reference)
#include <cuda_runtime.h>
#include <cuda_bf16.h>
#include <cstdint>

// ============================================================
// SimCLR loss on sm_103 (tcgen05 gated off by toolchain):
// normalize -> persistent, cp.async double-buffered bf16
// mma.sync GEMM over UPPER-TRIANGLE tiles of z z^T with fused
// exp/denominator (row+col) epilogue -> log reduce.
// B=4096, D=128, ROWS=8192, T=0.1.
// ============================================================

#define ROWS_TOTAL 8192
#define BHALF 4096
#define DIM 128
#define TILE 128
#define NTILES 64
#define NUPPER (NTILES * (NTILES + 1) / 2)   // 2080
#define INV_T 10.0f

#define TILE_BYTES 32768          // 128 rows x 256B (swizzled, no pad)
#define BUF_BYTES  (2 * TILE_BYTES)
#define SMEM_RED   (2 * BUF_BYTES)           // 131072: sRow/sCol floats
#define SMEM_TOTAL (SMEM_RED + 256 * 4)      // 132096

// ---------------- device scratch ----------------
__device__ __align__(16) __nv_bfloat16 g_z[ROWS_TOTAL * DIM];
__device__ float g_denom[ROWS_TOTAL];
__device__ float g_pos[ROWS_TOTAL];

// ---------------- helpers ----------------
__device__ __forceinline__ uint32_t smem_u32(const void* p) {
    uint32_t a;
    asm("{ .reg .u64 t; cvta.to.shared.u64 t, %1; cvt.u32.u64 %0, t; }"
        : "=r"(a) : "l"(p));
    return a;
}

#define LDSM_X4(r0, r1, r2, r3, addr) \
    asm volatile("ldmatrix.sync.aligned.m8n8.x4.shared.b16 {%0,%1,%2,%3}, [%4];" \
        : "=r"(r0), "=r"(r1), "=r"(r2), "=r"(r3) : "r"(addr))

#define CP_ASYNC_16(dst, src) \
    asm volatile("cp.async.cg.shared.global [%0], [%1], 16;" \
        :: "r"(dst), "l"(src))
#define CP_COMMIT() asm volatile("cp.async.commit_group;" ::: "memory")
#define CP_WAIT1()  asm volatile("cp.async.wait_group 1;" ::: "memory")

__device__ __forceinline__ void mma16816(float* c, const uint32_t* a, const uint32_t* b) {
    asm volatile(
        "mma.sync.aligned.m16n8k16.row.col.f32.bf16.bf16.f32 "
        "{%0,%1,%2,%3}, {%4,%5,%6,%7}, {%8,%9}, {%0,%1,%2,%3};"
        : "+f"(c[0]), "+f"(c[1]), "+f"(c[2]), "+f"(c[3])
        : "r"(a[0]), "r"(a[1]), "r"(a[2]), "r"(a[3]), "r"(b[0]), "r"(b[1]));
}

// swizzled smem byte offset: row r (0..127), 16B chunk c (0..15)
__device__ __forceinline__ uint32_t sw_off(int r, int c) {
    return (uint32_t)(r * 256 + ((c ^ (r & 7)) << 4));
}

// upper-triangle tile decode: t -> (m, n), m <= n
__device__ __forceinline__ void decode_tile(int t, int& m, int& n) {
    int mm = 0;
    while (t >= NTILES - mm) { t -= NTILES - mm; mm++; }
    m = mm; n = mm + t;
}

// ---------------- kernel 1: normalize (4 rows/warp, MLP=4) ----------------
__global__ void simclr_normalize_kernel(const float* __restrict__ xi,
                                        const float* __restrict__ xj)
{
    int w = (blockIdx.x * blockDim.x + threadIdx.x) >> 5;  // 0..2047
    int lane = threadIdx.x & 31;
    int row0 = w * 4;
    const float* base = (row0 < BHALF) ? (xi + (size_t)row0 * DIM)
                                       : (xj + (size_t)(row0 - BHALF) * DIM);

    float4 v[4];
    #pragma unroll
    for (int j = 0; j < 4; j++)
        v[j] = reinterpret_cast<const float4*>(base + j * DIM)[lane];

    float ss[4];
    #pragma unroll
    for (int j = 0; j < 4; j++)
        ss[j] = v[j].x * v[j].x + v[j].y * v[j].y + v[j].z * v[j].z + v[j].w * v[j].w;
    #pragma unroll
    for (int o = 16; o; o >>= 1)
        #pragma unroll
        for (int j = 0; j < 4; j++)
            ss[j] += __shfl_xor_sync(0xFFFFFFFFu, ss[j], o);

    #pragma unroll
    for (int j = 0; j < 4; j++) {
        float inv = rsqrtf(ss[j]);   // norm ~11; eps clamp can never bind
        __nv_bfloat162* dst =
            reinterpret_cast<__nv_bfloat162*>(g_z + (size_t)(row0 + j) * DIM);
        dst[lane * 2 + 0] = __floats2bfloat162_rn(v[j].x * inv, v[j].y * inv);
        dst[lane * 2 + 1] = __floats2bfloat162_rn(v[j].z * inv, v[j].w * inv);
    }
    if (lane < 4) g_denom[row0 + lane] = 0.0f;
}

// ---------------- kernel 2: persistent fused GEMM ----------------
// 512 threads, 16 warps (4 m-groups x 4 n-groups), warp tile 32x32.
// Double-buffered cp.async tile pipeline across the CTA's tile list.

__device__ __forceinline__ void issue_tile_loads(uint32_t smemBase, int buf,
                                                 int mTile, int nTile, int tid)
{
    const char* gA = reinterpret_cast<const char*>(g_z) + (size_t)mTile * TILE * DIM * 2;
    const char* gB = reinterpret_cast<const char*>(g_z) + (size_t)nTile * TILE * DIM * 2;
    uint32_t aB = smemBase + buf * BUF_BYTES;
    uint32_t bB = aB + TILE_BYTES;
    #pragma unroll
    for (int i = 0; i < 4; i++) {
        int idx = tid + i * 512;          // 0..2047 chunk id
        int r = idx >> 4, c = idx & 15;
        uint32_t so = sw_off(r, c);
        CP_ASYNC_16(aB + so, gA + idx * 16);
        CP_ASYNC_16(bB + so, gB + idx * 16);
    }
}

__global__ void __launch_bounds__(512, 1)
simclr_gemm_kernel()
{
    extern __shared__ char ds[];
    float* sRow = reinterpret_cast<float*>(ds + SMEM_RED);
    float* sCol = sRow + 128;

    int tid = threadIdx.x;
    int wid = tid >> 5;
    int lane = tid & 31;
    int warpM = wid & 3;
    int warpN = wid >> 2;
    int grp = lane >> 3;
    int rin = lane & 7;
    int g = lane >> 2;
    int q4 = lane & 3;
    uint32_t smemBase = smem_u32(ds);

    if (tid < 128) sRow[tid] = 0.0f;
    else if (tid < 256) sCol[tid - 128] = 0.0f;

    int t = blockIdx.x;
    int stride = gridDim.x;
    int mT = 0, nT = 0;
    if (t < NUPPER) {
        decode_tile(t, mT, nT);
        issue_tile_loads(smemBase, 0, mT, nT, tid);
    }
    CP_COMMIT();

    int buf = 0;
    for (; t < NUPPER; t += stride) {
        int tn = t + stride;
        int mN = 0, nN = 0;
        if (tn < NUPPER) {
            decode_tile(tn, mN, nN);
            issue_tile_loads(smemBase, buf ^ 1, mN, nN, tid);
        }
        CP_COMMIT();
        CP_WAIT1();
        __syncthreads();   // current buffer fully loaded; prior zeroing visible

        int rowBase = mT * TILE;
        int colBase = nT * TILE;
        bool isDiag = (mT == nT);
        bool isPart = (nT == (mT ^ (BHALF / TILE)));

        uint32_t aBase = smemBase + buf * BUF_BYTES;
        uint32_t bBase = aBase + TILE_BYTES;

        float acc[2][4][4];
        #pragma unroll
        for (int mi = 0; mi < 2; mi++)
            #pragma unroll
            for (int ni = 0; ni < 4; ni++)
                #pragma unroll
                for (int e = 0; e < 4; e++)
                    acc[mi][ni][e] = 0.0f;

        #pragma unroll
        for (int ks = 0; ks < 8; ks++) {
            uint32_t a[2][4];
            #pragma unroll
            for (int mi = 0; mi < 2; mi++) {
                int R = warpM * 32 + mi * 16 + rin + (grp & 1) * 8;
                int C = ks * 2 + (grp >> 1);
                LDSM_X4(a[mi][0], a[mi][1], a[mi][2], a[mi][3], aBase + sw_off(R, C));
            }
            uint32_t b[4][2];
            #pragma unroll
            for (int nb = 0; nb < 2; nb++) {
                int R = warpN * 32 + nb * 16 + rin + (grp >> 1) * 8;
                int C = ks * 2 + (grp & 1);
                LDSM_X4(b[nb * 2][0], b[nb * 2][1], b[nb * 2 + 1][0], b[nb * 2 + 1][1],
                        bBase + sw_off(R, C));
            }
            #pragma unroll
            for (int mi = 0; mi < 2; mi++)
                #pragma unroll
                for (int ni = 0; ni < 4; ni++)
                    mma16816(acc[mi][ni], a[mi], b[ni]);
        }

        // ---- epilogue ----
        if (isDiag) {
            #pragma unroll
            for (int mi = 0; mi < 2; mi++) {
                int r0 = warpM * 32 + mi * 16 + g;
                int grow0 = rowBase + r0;
                int grow1 = grow0 + 8;
                float s0 = 0.0f, s1 = 0.0f;
                #pragma unroll
                for (int ni = 0; ni < 4; ni++) {
                    int gc = colBase + warpN * 32 + ni * 8 + q4 * 2;
                    if (gc != grow0)     s0 += __expf(acc[mi][ni][0] * INV_T);
                    if (gc + 1 != grow0) s0 += __expf(acc[mi][ni][1] * INV_T);
                    if (gc != grow1)     s1 += __expf(acc[mi][ni][2] * INV_T);
                    if (gc + 1 != grow1) s1 += __expf(acc[mi][ni][3] * INV_T);
                }
                s0 += __shfl_xor_sync(0xFFFFFFFFu, s0, 1);
                s0 += __shfl_xor_sync(0xFFFFFFFFu, s0, 2);
                s1 += __shfl_xor_sync(0xFFFFFFFFu, s1, 1);
                s1 += __shfl_xor_sync(0xFFFFFFFFu, s1, 2);
                if (q4 == 0) {
                    atomicAdd(&sRow[r0], s0);
                    atomicAdd(&sRow[r0 + 8], s1);
                }
            }
        } else {
            float cp[4][2];
            #pragma unroll
            for (int ni = 0; ni < 4; ni++) { cp[ni][0] = 0.0f; cp[ni][1] = 0.0f; }

            #pragma unroll
            for (int mi = 0; mi < 2; mi++) {
                int r0 = warpM * 32 + mi * 16 + g;
                int grow0 = rowBase + r0;
                int grow1 = grow0 + 8;
                float s0 = 0.0f, s1 = 0.0f;
                #pragma unroll
                for (int ni = 0; ni < 4; ni++) {
                    float v0 = acc[mi][ni][0];
                    float v1 = acc[mi][ni][1];
                    float v2 = acc[mi][ni][2];
                    float v3 = acc[mi][ni][3];
                    if (isPart) {
                        int gc = colBase + warpN * 32 + ni * 8 + q4 * 2;
                        int part0 = grow0 ^ BHALF;
                        int part1 = grow1 ^ BHALF;
                        if (gc == part0)     { g_pos[grow0] = v0; g_pos[part0] = v0; }
                        if (gc + 1 == part0) { g_pos[grow0] = v1; g_pos[part0] = v1; }
                        if (gc == part1)     { g_pos[grow1] = v2; g_pos[part1] = v2; }
                        if (gc + 1 == part1) { g_pos[grow1] = v3; g_pos[part1] = v3; }
                    }
                    float e0 = __expf(v0 * INV_T);
                    float e1 = __expf(v1 * INV_T);
                    float e2 = __expf(v2 * INV_T);
                    float e3 = __expf(v3 * INV_T);
                    s0 += e0 + e1;
                    s1 += e2 + e3;
                    cp[ni][0] += e0 + e2;
                    cp[ni][1] += e1 + e3;
                }
                s0 += __shfl_xor_sync(0xFFFFFFFFu, s0, 1);
                s0 += __shfl_xor_sync(0xFFFFFFFFu, s0, 2);
                s1 += __shfl_xor_sync(0xFFFFFFFFu, s1, 1);
                s1 += __shfl_xor_sync(0xFFFFFFFFu, s1, 2);
                if (q4 == 0) {
                    atomicAdd(&sRow[r0], s0);
                    atomicAdd(&sRow[r0 + 8], s1);
                }
            }
            #pragma unroll
            for (int ni = 0; ni < 4; ni++) {
                #pragma unroll
                for (int e = 0; e < 2; e++) {
                    float v = cp[ni][e];
                    v += __shfl_xor_sync(0xFFFFFFFFu, v, 4);
                    v += __shfl_xor_sync(0xFFFFFFFFu, v, 8);
                    v += __shfl_xor_sync(0xFFFFFFFFu, v, 16);
                    if (g == 0)
                        atomicAdd(&sCol[warpN * 32 + ni * 8 + q4 * 2 + e], v);
                }
            }
        }

        __syncthreads();   // sRow/sCol complete; smem buffer reads done
        if (tid < 128) {
            atomicAdd(&g_denom[rowBase + tid], sRow[tid]);
            sRow[tid] = 0.0f;
        } else if (tid < 256) {
            if (!isDiag)
                atomicAdd(&g_denom[colBase + tid - 128], sCol[tid - 128]);
            sCol[tid - 128] = 0.0f;
        }

        mT = mN; nT = nN; buf ^= 1;
    }
}

// ---------------- kernel 3: final log + reduce ----------------
__global__ void simclr_reduce_kernel(float* __restrict__ out)
{
    __shared__ float sh[1024];
    float s = 0.0f;
    for (int i = threadIdx.x; i < ROWS_TOTAL; i += 1024)
        s += __logf(g_denom[i]) - INV_T * g_pos[i];
    sh[threadIdx.x] = s;
    __syncthreads();
    for (int o = 512; o; o >>= 1) {
        if (threadIdx.x < o) sh[threadIdx.x] += sh[threadIdx.x + o];
        __syncthreads();
    }
    if (threadIdx.x == 0)
        out[0] = sh[0] / (float)ROWS_TOTAL;
}

// ---------------- launch ----------------
extern "C" void kernel_launch(void* const* d_in, const int* in_sizes, int n_in,
                              void* d_out, int out_size)
{
    const float* xi = (const float*)d_in[0];
    const float* xj = (const float*)d_in[1];
    float* out = (float*)d_out;
    (void)in_sizes; (void)n_in; (void)out_size;

    int nsm = 148;
    cudaDeviceGetAttribute(&nsm, cudaDevAttrMultiProcessorCount, 0);

    cudaFuncSetAttribute(simclr_gemm_kernel,
                         cudaFuncAttributeMaxDynamicSharedMemorySize, SMEM_TOTAL);

    simclr_normalize_kernel<<<256, 256>>>(xi, xj);
    simclr_gemm_kernel<<<nsm, 512, SMEM_TOTAL>>>();
    simclr_reduce_kernel<<<1, 1024>>>(out);
}

// round 15
// speedup vs baseline: 1.2268x; 1.2268x over previous
#include <cuda_runtime.h>
#include <cuda_bf16.h>
#include <cstdint>

// ============================================================
// SimCLR loss on sm_103 (tcgen05 gated off by toolchain):
// normalize -> persistent row-chunked bf16 mma.sync GEMM over
// upper-triangle tiles of z z^T; A tile loaded once per chunk,
// B tiles double-buffered via cp.async; fused exp/denominator
// (row+col) epilogue -> log reduce.
// B=4096, D=128, ROWS=8192, T=0.1.
// ============================================================

#define ROWS_TOTAL 8192
#define BHALF 4096
#define DIM 128
#define TILE 128
#define NTILES 64
#define CHUNK 8
#define NCHUNKS 288               // sum_m ceil((64-m)/8)
#define INV_T 10.0f

#define TILE_BYTES 32768          // 128 rows x 256B swizzled
#define SMEM_A 0
#define SMEM_B0 TILE_BYTES
#define SMEM_B1 (2 * TILE_BYTES)
#define SMEM_RED (3 * TILE_BYTES)           // sRow[128], sCol[128]
#define SMEM_TOTAL (SMEM_RED + 256 * 4)     // 99328

// ---------------- device scratch ----------------
__device__ __align__(16) __nv_bfloat16 g_z[ROWS_TOTAL * DIM];
__device__ float g_denom[ROWS_TOTAL];
__device__ float g_pos[ROWS_TOTAL];

// ---------------- helpers ----------------
__device__ __forceinline__ uint32_t smem_u32(const void* p) {
    uint32_t a;
    asm("{ .reg .u64 t; cvta.to.shared.u64 t, %1; cvt.u32.u64 %0, t; }"
        : "=r"(a) : "l"(p));
    return a;
}

#define LDSM_X4(r0, r1, r2, r3, addr) \
    asm volatile("ldmatrix.sync.aligned.m8n8.x4.shared.b16 {%0,%1,%2,%3}, [%4];" \
        : "=r"(r0), "=r"(r1), "=r"(r2), "=r"(r3) : "r"(addr))

#define CP_ASYNC_16(dst, src) \
    asm volatile("cp.async.cg.shared.global [%0], [%1], 16;" \
        :: "r"(dst), "l"(src))
#define CP_COMMIT() asm volatile("cp.async.commit_group;" ::: "memory")
#define CP_WAIT(n)  asm volatile("cp.async.wait_group %0;" :: "n"(n) : "memory")

__device__ __forceinline__ void mma16816(float* c, const uint32_t* a, const uint32_t* b) {
    asm volatile(
        "mma.sync.aligned.m16n8k16.row.col.f32.bf16.bf16.f32 "
        "{%0,%1,%2,%3}, {%4,%5,%6,%7}, {%8,%9}, {%0,%1,%2,%3};"
        : "+f"(c[0]), "+f"(c[1]), "+f"(c[2]), "+f"(c[3])
        : "r"(a[0]), "r"(a[1]), "r"(a[2]), "r"(a[3]), "r"(b[0]), "r"(b[1]));
}

// swizzled smem byte offset: row r (0..127), 16B chunk c (0..15)
__device__ __forceinline__ uint32_t sw_off(int r, int c) {
    return (uint32_t)(r * 256 + ((c ^ (r & 7)) << 4));
}

// cp.async one 128x128 bf16 tile (32KB) into swizzled smem; 256 threads
__device__ __forceinline__ void cp_tile(uint32_t dstBase, const __nv_bfloat16* src, int tid) {
    const char* g = reinterpret_cast<const char*>(src);
    #pragma unroll
    for (int i = 0; i < 8; i++) {
        int idx = tid + i * 256;           // 0..2047 16B-chunk id
        int r = idx >> 4, c = idx & 15;
        CP_ASYNC_16(dstBase + sw_off(r, c), g + idx * 16);
    }
}

// ---------------- kernel 1: normalize + zero denom ----------------
__global__ void simclr_normalize_kernel(const float* __restrict__ xi,
                                        const float* __restrict__ xj)
{
    int warp = (blockIdx.x * blockDim.x + threadIdx.x) >> 5;
    int lane = threadIdx.x & 31;
    if (warp >= ROWS_TOTAL) return;

    const float* src = (warp < BHALF) ? (xi + (size_t)warp * DIM)
                                      : (xj + (size_t)(warp - BHALF) * DIM);
    float4 v = reinterpret_cast<const float4*>(src)[lane];
    float ss = v.x * v.x + v.y * v.y + v.z * v.z + v.w * v.w;
    #pragma unroll
    for (int o = 16; o; o >>= 1)
        ss += __shfl_xor_sync(0xFFFFFFFFu, ss, o);
    float inv = rsqrtf(ss);   // norm ~11; eps clamp can never bind

    __nv_bfloat162* dst = reinterpret_cast<__nv_bfloat162*>(g_z + (size_t)warp * DIM);
    dst[lane * 2 + 0] = __floats2bfloat162_rn(v.x * inv, v.y * inv);
    dst[lane * 2 + 1] = __floats2bfloat162_rn(v.z * inv, v.w * inv);

    if (lane == 0) g_denom[warp] = 0.0f;
}

// ---------------- kernel 2: persistent chunked fused GEMM ----------------
// 8 warps (4 m-groups x 2 n-groups), warp tile 32x64, occ 2.
__global__ void __launch_bounds__(256, 2)
simclr_gemm_kernel()
{
    extern __shared__ char ds[];
    float* sRow = reinterpret_cast<float*>(ds + SMEM_RED);
    float* sCol = sRow + 128;
    uint32_t smemBase = smem_u32(ds);

    int tid = threadIdx.x;
    int wid = tid >> 5;
    int lane = tid & 31;
    int warpM = wid & 3;
    int warpN = wid >> 2;
    int grp = lane >> 3;
    int rin = lane & 7;
    int g = lane >> 2;
    int q4 = lane & 3;

    // decode chunk: row m, tiles [nStart, nStart+cnt), all within row m
    int cid = blockIdx.x;
    int m = 0;
    for (;;) {
        int c = (NTILES - m + CHUNK - 1) >> 3;
        if (cid < c) break;
        cid -= c; m++;
    }
    int nStart = m + cid * CHUNK;
    int cnt = min(CHUNK, NTILES - m - cid * CHUNK);
    int rowBase = m * TILE;

    if (tid < 128) sRow[tid] = 0.0f;
    else if (tid < 256) sCol[tid - 128] = 0.0f;

    // prologue loads: A + B0 (group), B1 (group)
    cp_tile(smemBase + SMEM_A, g_z + (size_t)m * TILE * DIM, tid);
    cp_tile(smemBase + SMEM_B0, g_z + (size_t)nStart * TILE * DIM, tid);
    CP_COMMIT();
    if (cnt > 1) {
        cp_tile(smemBase + SMEM_B1, g_z + (size_t)(nStart + 1) * TILE * DIM, tid);
        CP_COMMIT();
    }

    uint32_t aBase = smemBase + SMEM_A;

    for (int i = 0; i < cnt; i++) {
        if (i + 1 < cnt) { CP_WAIT(1); } else { CP_WAIT(0); }
        __syncthreads();   // tile i resident for all threads; sCol zeroing visible

        int nT = nStart + i;
        int colBase = nT * TILE;
        bool isDiag = (m == nT);
        bool isPart = (nT == (m ^ (BHALF / TILE)));
        uint32_t bBase = smemBase + ((i & 1) ? SMEM_B1 : SMEM_B0);

        float acc[2][8][4];
        #pragma unroll
        for (int mi = 0; mi < 2; mi++)
            #pragma unroll
            for (int ni = 0; ni < 8; ni++)
                #pragma unroll
                for (int e = 0; e < 4; e++)
                    acc[mi][ni][e] = 0.0f;

        #pragma unroll
        for (int ks = 0; ks < 8; ks++) {
            uint32_t a[2][4];
            #pragma unroll
            for (int mi = 0; mi < 2; mi++) {
                int R = warpM * 32 + mi * 16 + rin + (grp & 1) * 8;
                int C = ks * 2 + (grp >> 1);
                LDSM_X4(a[mi][0], a[mi][1], a[mi][2], a[mi][3], aBase + sw_off(R, C));
            }
            uint32_t b[8][2];
            #pragma unroll
            for (int nb = 0; nb < 4; nb++) {
                int R = warpN * 64 + nb * 16 + rin + (grp >> 1) * 8;
                int C = ks * 2 + (grp & 1);
                LDSM_X4(b[nb * 2][0], b[nb * 2][1], b[nb * 2 + 1][0], b[nb * 2 + 1][1],
                        bBase + sw_off(R, C));
            }
            #pragma unroll
            for (int mi = 0; mi < 2; mi++)
                #pragma unroll
                for (int ni = 0; ni < 8; ni++)
                    mma16816(acc[mi][ni], a[mi], b[ni]);
        }

        // ---- epilogue ----
        if (isDiag) {
            #pragma unroll
            for (int mi = 0; mi < 2; mi++) {
                int r0 = warpM * 32 + mi * 16 + g;
                int grow0 = rowBase + r0;
                int grow1 = grow0 + 8;
                float s0 = 0.0f, s1 = 0.0f;
                #pragma unroll
                for (int ni = 0; ni < 8; ni++) {
                    int gc = colBase + warpN * 64 + ni * 8 + q4 * 2;
                    if (gc != grow0)     s0 += __expf(acc[mi][ni][0] * INV_T);
                    if (gc + 1 != grow0) s0 += __expf(acc[mi][ni][1] * INV_T);
                    if (gc != grow1)     s1 += __expf(acc[mi][ni][2] * INV_T);
                    if (gc + 1 != grow1) s1 += __expf(acc[mi][ni][3] * INV_T);
                }
                s0 += __shfl_xor_sync(0xFFFFFFFFu, s0, 1);
                s0 += __shfl_xor_sync(0xFFFFFFFFu, s0, 2);
                s1 += __shfl_xor_sync(0xFFFFFFFFu, s1, 1);
                s1 += __shfl_xor_sync(0xFFFFFFFFu, s1, 2);
                if (q4 == 0) {
                    atomicAdd(&sRow[r0], s0);
                    atomicAdd(&sRow[r0 + 8], s1);
                }
            }
        } else {
            float cp[8][2];
            #pragma unroll
            for (int ni = 0; ni < 8; ni++) { cp[ni][0] = 0.0f; cp[ni][1] = 0.0f; }

            #pragma unroll
            for (int mi = 0; mi < 2; mi++) {
                int r0 = warpM * 32 + mi * 16 + g;
                int grow0 = rowBase + r0;
                int grow1 = grow0 + 8;
                float s0 = 0.0f, s1 = 0.0f;
                #pragma unroll
                for (int ni = 0; ni < 8; ni++) {
                    float v0 = acc[mi][ni][0];
                    float v1 = acc[mi][ni][1];
                    float v2 = acc[mi][ni][2];
                    float v3 = acc[mi][ni][3];
                    if (isPart) {
                        int gc = colBase + warpN * 64 + ni * 8 + q4 * 2;
                        int part0 = grow0 ^ BHALF;
                        int part1 = grow1 ^ BHALF;
                        if (gc == part0)     { g_pos[grow0] = v0; g_pos[part0] = v0; }
                        if (gc + 1 == part0) { g_pos[grow0] = v1; g_pos[part0] = v1; }
                        if (gc == part1)     { g_pos[grow1] = v2; g_pos[part1] = v2; }
                        if (gc + 1 == part1) { g_pos[grow1] = v3; g_pos[part1] = v3; }
                    }
                    float e0 = __expf(v0 * INV_T);
                    float e1 = __expf(v1 * INV_T);
                    float e2 = __expf(v2 * INV_T);
                    float e3 = __expf(v3 * INV_T);
                    s0 += e0 + e1;
                    s1 += e2 + e3;
                    cp[ni][0] += e0 + e2;
                    cp[ni][1] += e1 + e3;
                }
                s0 += __shfl_xor_sync(0xFFFFFFFFu, s0, 1);
                s0 += __shfl_xor_sync(0xFFFFFFFFu, s0, 2);
                s1 += __shfl_xor_sync(0xFFFFFFFFu, s1, 1);
                s1 += __shfl_xor_sync(0xFFFFFFFFu, s1, 2);
                if (q4 == 0) {
                    atomicAdd(&sRow[r0], s0);
                    atomicAdd(&sRow[r0 + 8], s1);
                }
            }
            #pragma unroll
            for (int ni = 0; ni < 8; ni++) {
                #pragma unroll
                for (int e = 0; e < 2; e++) {
                    float v = cp[ni][e];
                    v += __shfl_xor_sync(0xFFFFFFFFu, v, 4);
                    v += __shfl_xor_sync(0xFFFFFFFFu, v, 8);
                    v += __shfl_xor_sync(0xFFFFFFFFu, v, 16);
                    if (g == 0)
                        atomicAdd(&sCol[warpN * 64 + ni * 8 + q4 * 2 + e], v);
                }
            }
        }

        __syncthreads();   // epilogue atomics done; all B-buffer reads done

        // flush col sums for this tile; keep row sums accumulating
        if (tid >= 128 && tid < 256) {
            if (!isDiag)
                atomicAdd(&g_denom[colBase + tid - 128], sCol[tid - 128]);
            sCol[tid - 128] = 0.0f;
        }

        // prefetch tile i+2 into the buffer just freed (all reads done)
        if (i + 2 < cnt) {
            cp_tile(smemBase + ((i & 1) ? SMEM_B1 : SMEM_B0),
                    g_z + (size_t)(nStart + i + 2) * TILE * DIM, tid);
            CP_COMMIT();
        }
    }

    // flush accumulated row sums once per chunk
    __syncthreads();
    if (tid < 128)
        atomicAdd(&g_denom[rowBase + tid], sRow[tid]);
}

// ---------------- kernel 3: final log + reduce ----------------
__global__ void simclr_reduce_kernel(float* __restrict__ out)
{
    __shared__ float sh[1024];
    float s = 0.0f;
    for (int i = threadIdx.x; i < ROWS_TOTAL; i += 1024)
        s += __logf(g_denom[i]) - INV_T * g_pos[i];
    sh[threadIdx.x] = s;
    __syncthreads();
    for (int o = 512; o; o >>= 1) {
        if (threadIdx.x < o) sh[threadIdx.x] += sh[threadIdx.x + o];
        __syncthreads();
    }
    if (threadIdx.x == 0)
        out[0] = sh[0] / (float)ROWS_TOTAL;
}

// ---------------- launch ----------------
extern "C" void kernel_launch(void* const* d_in, const int* in_sizes, int n_in,
                              void* d_out, int out_size)
{
    const float* xi = (const float*)d_in[0];
    const float* xj = (const float*)d_in[1];
    float* out = (float*)d_out;
    (void)in_sizes; (void)n_in; (void)out_size;

    cudaFuncSetAttribute(simclr_gemm_kernel,
                         cudaFuncAttributeMaxDynamicSharedMemorySize, SMEM_TOTAL);

    simclr_normalize_kernel<<<1024, 256>>>(xi, xj);
    simclr_gemm_kernel<<<NCHUNKS, 256, SMEM_TOTAL>>>();
    simclr_reduce_kernel<<<1, 1024>>>(out);
}

// round 16
// speedup vs baseline: 1.3860x; 1.1298x over previous
#include <cuda_runtime.h>
#include <cuda_bf16.h>
#include <cstdint>

// ============================================================
// SimCLR loss on sm_103 (tcgen05 gated off by toolchain):
// normalize -> persistent row-chunked bf16 mma.sync GEMM over
// upper-triangle tiles of z z^T; A loaded once per chunk, B
// distance-1 double-buffered cp.async (ONE barrier per tile);
// epilogue: exp + register row sums (flushed once per chunk) +
// reduce-scatter column sums -> direct global atomics.
// B=4096, D=128, ROWS=8192, T=0.1.
// ============================================================

#define ROWS_TOTAL 8192
#define BHALF 4096
#define DIM 128
#define TILE 128
#define NTILES 64
#define CHUNK 8
#define NCHUNKS 288               // sum_m ceil((64-m)/8)
#define INV_T 10.0f

#define TILE_BYTES 32768          // 128 rows x 256B swizzled
#define SMEM_A 0
#define SMEM_B0 TILE_BYTES
#define SMEM_B1 (2 * TILE_BYTES)
#define SMEM_TOTAL (3 * TILE_BYTES)   // 98304

// ---------------- device scratch ----------------
__device__ __align__(16) __nv_bfloat16 g_z[ROWS_TOTAL * DIM];
__device__ float g_denom[ROWS_TOTAL];
__device__ float g_pos[ROWS_TOTAL];

// ---------------- helpers ----------------
__device__ __forceinline__ uint32_t smem_u32(const void* p) {
    uint32_t a;
    asm("{ .reg .u64 t; cvta.to.shared.u64 t, %1; cvt.u32.u64 %0, t; }"
        : "=r"(a) : "l"(p));
    return a;
}

#define LDSM_X4(r0, r1, r2, r3, addr) \
    asm volatile("ldmatrix.sync.aligned.m8n8.x4.shared.b16 {%0,%1,%2,%3}, [%4];" \
        : "=r"(r0), "=r"(r1), "=r"(r2), "=r"(r3) : "r"(addr))

#define CP_ASYNC_16(dst, src) \
    asm volatile("cp.async.cg.shared.global [%0], [%1], 16;" \
        :: "r"(dst), "l"(src))
#define CP_COMMIT() asm volatile("cp.async.commit_group;" ::: "memory")
#define CP_WAIT0()  asm volatile("cp.async.wait_group 0;" ::: "memory")

__device__ __forceinline__ void mma16816(float* c, const uint32_t* a, const uint32_t* b) {
    asm volatile(
        "mma.sync.aligned.m16n8k16.row.col.f32.bf16.bf16.f32 "
        "{%0,%1,%2,%3}, {%4,%5,%6,%7}, {%8,%9}, {%0,%1,%2,%3};"
        : "+f"(c[0]), "+f"(c[1]), "+f"(c[2]), "+f"(c[3])
        : "r"(a[0]), "r"(a[1]), "r"(a[2]), "r"(a[3]), "r"(b[0]), "r"(b[1]));
}

// swizzled smem byte offset: row r (0..127), 16B chunk c (0..15)
__device__ __forceinline__ uint32_t sw_off(int r, int c) {
    return (uint32_t)(r * 256 + ((c ^ (r & 7)) << 4));
}

// cp.async one 128x128 bf16 tile (32KB) into swizzled smem; 256 threads
__device__ __forceinline__ void cp_tile(uint32_t dstBase, const __nv_bfloat16* src, int tid) {
    const char* g = reinterpret_cast<const char*>(src);
    #pragma unroll
    for (int i = 0; i < 8; i++) {
        int idx = tid + i * 256;           // 0..2047 16B-chunk id
        int r = idx >> 4, c = idx & 15;
        CP_ASYNC_16(dstBase + sw_off(r, c), g + idx * 16);
    }
}

// ---------------- kernel 1: normalize + zero denom ----------------
__global__ void simclr_normalize_kernel(const float* __restrict__ xi,
                                        const float* __restrict__ xj)
{
    int warp = (blockIdx.x * blockDim.x + threadIdx.x) >> 5;
    int lane = threadIdx.x & 31;
    if (warp >= ROWS_TOTAL) return;

    const float* src = (warp < BHALF) ? (xi + (size_t)warp * DIM)
                                      : (xj + (size_t)(warp - BHALF) * DIM);
    float4 v = reinterpret_cast<const float4*>(src)[lane];
    float ss = v.x * v.x + v.y * v.y + v.z * v.z + v.w * v.w;
    #pragma unroll
    for (int o = 16; o; o >>= 1)
        ss += __shfl_xor_sync(0xFFFFFFFFu, ss, o);
    float inv = rsqrtf(ss);   // norm ~11; eps clamp can never bind

    __nv_bfloat162* dst = reinterpret_cast<__nv_bfloat162*>(g_z + (size_t)warp * DIM);
    dst[lane * 2 + 0] = __floats2bfloat162_rn(v.x * inv, v.y * inv);
    dst[lane * 2 + 1] = __floats2bfloat162_rn(v.z * inv, v.w * inv);

    if (lane == 0) g_denom[warp] = 0.0f;
}

// ---------------- kernel 2: persistent chunked fused GEMM ----------------
// 8 warps (4 m-groups x 2 n-groups), warp tile 32x64, occ 2.
__global__ void __launch_bounds__(256, 2)
simclr_gemm_kernel()
{
    extern __shared__ char ds[];
    uint32_t smemBase = smem_u32(ds);

    int tid = threadIdx.x;
    int wid = tid >> 5;
    int lane = tid & 31;
    int warpM = wid & 3;
    int warpN = wid >> 2;
    int grp = lane >> 3;
    int rin = lane & 7;
    int g = lane >> 2;
    int q4 = lane & 3;

    // reduce-scatter lane coordinates (bits of g)
    int sel1 = (lane >> 2) & 1;
    int sel2 = (lane >> 3) & 1;
    int sel3 = (lane >> 4) & 1;
    int niOwn = sel1 * 4 + sel2 * 2 + sel3;

    // decode chunk: row m, tiles [nStart, nStart+cnt), all within row m
    int cid = blockIdx.x;
    int m = 0;
    for (;;) {
        int c = (NTILES - m + CHUNK - 1) >> 3;
        if (cid < c) break;
        cid -= c; m++;
    }
    int nStart = m + cid * CHUNK;
    int cnt = min(CHUNK, NTILES - m - cid * CHUNK);
    int rowBase = m * TILE;

    // prologue: A + first B tile in one group
    cp_tile(smemBase + SMEM_A, g_z + (size_t)m * TILE * DIM, tid);
    cp_tile(smemBase + SMEM_B0, g_z + (size_t)nStart * TILE * DIM, tid);
    CP_COMMIT();

    uint32_t aBase = smemBase + SMEM_A;

    // per-thread row sums, accumulated over the whole chunk
    float rs[2][2] = {{0.0f, 0.0f}, {0.0f, 0.0f}};

    for (int i = 0; i < cnt; i++) {
        CP_WAIT0();
        __syncthreads();   // tile i resident; all warps done with tile i-1

        // distance-1 prefetch into the other buffer (tile i-1's reads done)
        if (i + 1 < cnt) {
            cp_tile(smemBase + (((i + 1) & 1) ? SMEM_B1 : SMEM_B0),
                    g_z + (size_t)(nStart + i + 1) * TILE * DIM, tid);
            CP_COMMIT();
        }

        int nT = nStart + i;
        int colBase = nT * TILE;
        bool isDiag = (m == nT);
        bool isPart = (nT == (m ^ (BHALF / TILE)));
        uint32_t bBase = smemBase + ((i & 1) ? SMEM_B1 : SMEM_B0);

        float acc[2][8][4];
        #pragma unroll
        for (int mi = 0; mi < 2; mi++)
            #pragma unroll
            for (int ni = 0; ni < 8; ni++)
                #pragma unroll
                for (int e = 0; e < 4; e++)
                    acc[mi][ni][e] = 0.0f;

        #pragma unroll
        for (int ks = 0; ks < 8; ks++) {
            uint32_t a[2][4];
            #pragma unroll
            for (int mi = 0; mi < 2; mi++) {
                int R = warpM * 32 + mi * 16 + rin + (grp & 1) * 8;
                int C = ks * 2 + (grp >> 1);
                LDSM_X4(a[mi][0], a[mi][1], a[mi][2], a[mi][3], aBase + sw_off(R, C));
            }
            uint32_t b[8][2];
            #pragma unroll
            for (int nb = 0; nb < 4; nb++) {
                int R = warpN * 64 + nb * 16 + rin + (grp >> 1) * 8;
                int C = ks * 2 + (grp & 1);
                LDSM_X4(b[nb * 2][0], b[nb * 2][1], b[nb * 2 + 1][0], b[nb * 2 + 1][1],
                        bBase + sw_off(R, C));
            }
            #pragma unroll
            for (int mi = 0; mi < 2; mi++)
                #pragma unroll
                for (int ni = 0; ni < 8; ni++)
                    mma16816(acc[mi][ni], a[mi], b[ni]);
        }

        // ---- epilogue (no barriers) ----
        if (isDiag) {
            // row sums only; skip diagonal element
            #pragma unroll
            for (int mi = 0; mi < 2; mi++) {
                int grow0 = rowBase + warpM * 32 + mi * 16 + g;
                int grow1 = grow0 + 8;
                #pragma unroll
                for (int ni = 0; ni < 8; ni++) {
                    int gc = colBase + warpN * 64 + ni * 8 + q4 * 2;
                    if (gc != grow0)     rs[mi][0] += __expf(acc[mi][ni][0] * INV_T);
                    if (gc + 1 != grow0) rs[mi][0] += __expf(acc[mi][ni][1] * INV_T);
                    if (gc != grow1)     rs[mi][1] += __expf(acc[mi][ni][2] * INV_T);
                    if (gc + 1 != grow1) rs[mi][1] += __expf(acc[mi][ni][3] * INV_T);
                }
            }
        } else {
            float cp[8][2];
            #pragma unroll
            for (int ni = 0; ni < 8; ni++) { cp[ni][0] = 0.0f; cp[ni][1] = 0.0f; }

            #pragma unroll
            for (int mi = 0; mi < 2; mi++) {
                int grow0 = rowBase + warpM * 32 + mi * 16 + g;
                int grow1 = grow0 + 8;
                #pragma unroll
                for (int ni = 0; ni < 8; ni++) {
                    float v0 = acc[mi][ni][0];
                    float v1 = acc[mi][ni][1];
                    float v2 = acc[mi][ni][2];
                    float v3 = acc[mi][ni][3];
                    if (isPart) {
                        int gc = colBase + warpN * 64 + ni * 8 + q4 * 2;
                        int part0 = grow0 ^ BHALF;
                        int part1 = grow1 ^ BHALF;
                        if (gc == part0)     { g_pos[grow0] = v0; g_pos[part0] = v0; }
                        if (gc + 1 == part0) { g_pos[grow0] = v1; g_pos[part0] = v1; }
                        if (gc == part1)     { g_pos[grow1] = v2; g_pos[part1] = v2; }
                        if (gc + 1 == part1) { g_pos[grow1] = v3; g_pos[part1] = v3; }
                    }
                    float e0 = __expf(v0 * INV_T);
                    float e1 = __expf(v1 * INV_T);
                    float e2 = __expf(v2 * INV_T);
                    float e3 = __expf(v3 * INV_T);
                    rs[mi][0] += e0 + e1;
                    rs[mi][1] += e2 + e3;
                    cp[ni][0] += e0 + e2;
                    cp[ni][1] += e1 + e3;
                }
            }

            // ---- column reduce-scatter over the 8 g-groups (14 shfls) ----
            // round 1: partner xor 4; sel1==0 keeps ni 0..3, gives 4..7
            #pragma unroll
            for (int k = 0; k < 4; k++)
                #pragma unroll
                for (int e = 0; e < 2; e++) {
                    float send = sel1 ? cp[k][e] : cp[k + 4][e];
                    float recv = __shfl_xor_sync(0xFFFFFFFFu, send, 4);
                    cp[sel1 * 4 + k][e] += recv;
                }
            int base1 = sel1 * 4;
            // round 2: partner xor 8; sel2==0 keeps lower 2 of the live 4
            #pragma unroll
            for (int k = 0; k < 2; k++)
                #pragma unroll
                for (int e = 0; e < 2; e++) {
                    float send = sel2 ? cp[base1 + k][e] : cp[base1 + 2 + k][e];
                    float recv = __shfl_xor_sync(0xFFFFFFFFu, send, 8);
                    cp[base1 + sel2 * 2 + k][e] += recv;
                }
            int base2 = base1 + sel2 * 2;
            // round 3: partner xor 16; sel3==0 keeps base2, gives base2+1
            #pragma unroll
            for (int e = 0; e < 2; e++) {
                float send = sel3 ? cp[base2][e] : cp[base2 + 1][e];
                float recv = __shfl_xor_sync(0xFFFFFFFFu, send, 16);
                cp[base2 + sel3][e] += recv;
            }
            // each lane owns 2 distinct columns -> direct global atomics
            int colBaseW = colBase + warpN * 64 + niOwn * 8 + q4 * 2;
            atomicAdd(&g_denom[colBaseW + 0], cp[base2 + sel3][0]);
            atomicAdd(&g_denom[colBaseW + 1], cp[base2 + sel3][1]);
        }
    }

    // ---- flush accumulated row sums once per chunk ----
    #pragma unroll
    for (int mi = 0; mi < 2; mi++) {
        #pragma unroll
        for (int h = 0; h < 2; h++) {
            float v = rs[mi][h];
            v += __shfl_xor_sync(0xFFFFFFFFu, v, 1);
            v += __shfl_xor_sync(0xFFFFFFFFu, v, 2);
            if (q4 == 0)
                atomicAdd(&g_denom[rowBase + warpM * 32 + mi * 16 + g + h * 8], v);
        }
    }
}

// ---------------- kernel 3: final log + reduce ----------------
__global__ void simclr_reduce_kernel(float* __restrict__ out)
{
    __shared__ float sh[1024];
    float s = 0.0f;
    for (int i = threadIdx.x; i < ROWS_TOTAL; i += 1024)
        s += __logf(g_denom[i]) - INV_T * g_pos[i];
    sh[threadIdx.x] = s;
    __syncthreads();
    for (int o = 512; o; o >>= 1) {
        if (threadIdx.x < o) sh[threadIdx.x] += sh[threadIdx.x + o];
        __syncthreads();
    }
    if (threadIdx.x == 0)
        out[0] = sh[0] / (float)ROWS_TOTAL;
}

// ---------------- launch ----------------
extern "C" void kernel_launch(void* const* d_in, const int* in_sizes, int n_in,
                              void* d_out, int out_size)
{
    const float* xi = (const float*)d_in[0];
    const float* xj = (const float*)d_in[1];
    float* out = (float*)d_out;
    (void)in_sizes; (void)n_in; (void)out_size;

    cudaFuncSetAttribute(simclr_gemm_kernel,
                         cudaFuncAttributeMaxDynamicSharedMemorySize, SMEM_TOTAL);

    simclr_normalize_kernel<<<1024, 256>>>(xi, xj);
    simclr_gemm_kernel<<<NCHUNKS, 256, SMEM_TOTAL>>>();
    simclr_reduce_kernel<<<1, 1024>>>(out);
}

// round 17
// speedup vs baseline: 1.5166x; 1.0942x over previous
#include <cuda_runtime.h>
#include <cuda_bf16.h>
#include <cstdint>

// ============================================================
// SimCLR loss, single fused persistent kernel on sm_103:
// phase 1: normalize rows, scaled by sqrt(10*log2(e)) so the
//          GEMM accumulator is directly the base-2 exponent
// phase 2: row-chunked bf16 mma.sync GEMM over upper-triangle
//          tiles of z z^T; A once per chunk, B double-buffered
//          cp.async; epilogue = raw EX2 + register row sums +
//          reduce-scatter column sums -> global atomics
// phase 3: CTA 0 log-reduce
// Grid barriers: monotonic-ticket spin (288 CTAs all resident).
// B=4096, D=128, ROWS=8192, T=0.1.
// ============================================================

#define ROWS_TOTAL 8192
#define BHALF 4096
#define DIM 128
#define TILE 128
#define NTILES 64
#define CHUNK 8
#define NCHUNKS 288               // sum_m ceil((64-m)/8); <= 296 resident slots
#define ROWS_PER_CTA 29           // ceil(8192/288)

// sqrt(10 * log2(e)) : acc = 10*log2(e)*sim ; 2^acc = exp(10*sim)
#define Z_SCALE 3.7982819f
#define LN2 0.69314718f

#define TILE_BYTES 32768          // 128 rows x 256B swizzled
#define SMEM_A 0
#define SMEM_B0 TILE_BYTES
#define SMEM_B1 (2 * TILE_BYTES)
#define SMEM_TOTAL (3 * TILE_BYTES)   // 98304

// ---------------- device scratch ----------------
__device__ __align__(16) __nv_bfloat16 g_z[ROWS_TOTAL * DIM];
__device__ float g_denom[ROWS_TOTAL];
__device__ float g_pos[ROWS_TOTAL];          // stores raw acc (=10*log2e*sim)
__device__ unsigned g_bar1, g_bar2;          // monotonic ticket counters

// ---------------- helpers ----------------
__device__ __forceinline__ uint32_t smem_u32(const void* p) {
    uint32_t a;
    asm("{ .reg .u64 t; cvta.to.shared.u64 t, %1; cvt.u32.u64 %0, t; }"
        : "=r"(a) : "l"(p));
    return a;
}

#define LDSM_X4(r0, r1, r2, r3, addr) \
    asm volatile("ldmatrix.sync.aligned.m8n8.x4.shared.b16 {%0,%1,%2,%3}, [%4];" \
        : "=r"(r0), "=r"(r1), "=r"(r2), "=r"(r3) : "r"(addr))

#define CP_ASYNC_16(dst, src) \
    asm volatile("cp.async.cg.shared.global [%0], [%1], 16;" \
        :: "r"(dst), "l"(src))
#define CP_COMMIT() asm volatile("cp.async.commit_group;" ::: "memory")
#define CP_WAIT0()  asm volatile("cp.async.wait_group 0;" ::: "memory")

__device__ __forceinline__ void mma16816(float* c, const uint32_t* a, const uint32_t* b) {
    asm volatile(
        "mma.sync.aligned.m16n8k16.row.col.f32.bf16.bf16.f32 "
        "{%0,%1,%2,%3}, {%4,%5,%6,%7}, {%8,%9}, {%0,%1,%2,%3};"
        : "+f"(c[0]), "+f"(c[1]), "+f"(c[2]), "+f"(c[3])
        : "r"(a[0]), "r"(a[1]), "r"(a[2]), "r"(a[3]), "r"(b[0]), "r"(b[1]));
}

// raw MUFU.EX2 (2^x) — the exponent scale is baked into g_z
__device__ __forceinline__ float ex2f(float x) {
    float y;
    asm("ex2.approx.ftz.f32 %0, %1;" : "=f"(y) : "f"(x));
    return y;
}

// swizzled smem byte offset: row r (0..127), 16B chunk c (0..15)
__device__ __forceinline__ uint32_t sw_off(int r, int c) {
    return (uint32_t)(r * 256 + ((c ^ (r & 7)) << 4));
}

// cp.async one 128x128 bf16 tile (32KB) into swizzled smem; 256 threads
__device__ __forceinline__ void cp_tile(uint32_t dstBase, const __nv_bfloat16* src, int tid) {
    const char* g = reinterpret_cast<const char*>(src);
    #pragma unroll
    for (int i = 0; i < 8; i++) {
        int idx = tid + i * 256;           // 0..2047 16B-chunk id
        int r = idx >> 4, c = idx & 15;
        CP_ASYNC_16(dstBase + sw_off(r, c), g + idx * 16);
    }
}

// monotonic-ticket grid barrier; replay-safe (counter never resets,
// launches on one stream serialize). All NCHUNKS CTAs are resident.
__device__ __forceinline__ void grid_barrier(unsigned* bar, int tid) {
    __threadfence();
    __syncthreads();
    if (tid == 0) {
        unsigned ticket = atomicAdd(bar, 1u);
        unsigned target = (ticket / NCHUNKS + 1u) * NCHUNKS;
        unsigned cur;
        do {
            asm volatile("ld.acquire.gpu.u32 %0, [%1];" : "=r"(cur) : "l"(bar));
        } while (cur < target);
    }
    __syncthreads();
}

// ---------------- the fused kernel ----------------
__global__ void __launch_bounds__(256, 2)
simclr_fused_kernel(const float* __restrict__ xi,
                    const float* __restrict__ xj,
                    float* __restrict__ out)
{
    extern __shared__ char ds[];
    uint32_t smemBase = smem_u32(ds);

    int tid = threadIdx.x;
    int wid = tid >> 5;
    int lane = tid & 31;

    // ================= phase 1: normalize (scaled) =================
    {
        int rBeg = blockIdx.x * ROWS_PER_CTA;
        int rEnd = min(rBeg + ROWS_PER_CTA, ROWS_TOTAL);
        for (int r = rBeg + wid; r < rEnd; r += 8) {
            const float* src = (r < BHALF) ? (xi + (size_t)r * DIM)
                                           : (xj + (size_t)(r - BHALF) * DIM);
            float4 v = reinterpret_cast<const float4*>(src)[lane];
            float ss = v.x * v.x + v.y * v.y + v.z * v.z + v.w * v.w;
            #pragma unroll
            for (int o = 16; o; o >>= 1)
                ss += __shfl_xor_sync(0xFFFFFFFFu, ss, o);
            // norm ~11 for D=128 gaussian rows; eps clamp can never bind
            float inv = rsqrtf(ss) * Z_SCALE;

            __nv_bfloat162* dst = reinterpret_cast<__nv_bfloat162*>(g_z + (size_t)r * DIM);
            dst[lane * 2 + 0] = __floats2bfloat162_rn(v.x * inv, v.y * inv);
            dst[lane * 2 + 1] = __floats2bfloat162_rn(v.z * inv, v.w * inv);
            if (lane == 0) g_denom[r] = 0.0f;
        }
    }

    grid_barrier(&g_bar1, tid);

    // ================= phase 2: chunked fused GEMM =================
    {
        int warpM = wid & 3;
        int warpN = wid >> 2;
        int grp = lane >> 3;
        int rin = lane & 7;
        int g = lane >> 2;
        int q4 = lane & 3;

        int sel1 = (lane >> 2) & 1;
        int sel2 = (lane >> 3) & 1;
        int sel3 = (lane >> 4) & 1;
        int niOwn = sel1 * 4 + sel2 * 2 + sel3;

        // decode chunk: row m, tiles [nStart, nStart+cnt)
        int cid = blockIdx.x;
        int m = 0;
        for (;;) {
            int c = (NTILES - m + CHUNK - 1) >> 3;
            if (cid < c) break;
            cid -= c; m++;
        }
        int nStart = m + cid * CHUNK;
        int cnt = min(CHUNK, NTILES - m - cid * CHUNK);
        int rowBase = m * TILE;

        cp_tile(smemBase + SMEM_A, g_z + (size_t)m * TILE * DIM, tid);
        cp_tile(smemBase + SMEM_B0, g_z + (size_t)nStart * TILE * DIM, tid);
        CP_COMMIT();

        uint32_t aBase = smemBase + SMEM_A;
        float rs[2][2] = {{0.0f, 0.0f}, {0.0f, 0.0f}};

        for (int i = 0; i < cnt; i++) {
            CP_WAIT0();
            __syncthreads();   // tile i resident; all warps done with tile i-1

            if (i + 1 < cnt) {
                cp_tile(smemBase + (((i + 1) & 1) ? SMEM_B1 : SMEM_B0),
                        g_z + (size_t)(nStart + i + 1) * TILE * DIM, tid);
                CP_COMMIT();
            }

            int nT = nStart + i;
            int colBase = nT * TILE;
            bool isDiag = (m == nT);
            bool isPart = (nT == (m ^ (BHALF / TILE)));
            uint32_t bBase = smemBase + ((i & 1) ? SMEM_B1 : SMEM_B0);

            float acc[2][8][4];
            #pragma unroll
            for (int mi = 0; mi < 2; mi++)
                #pragma unroll
                for (int ni = 0; ni < 8; ni++)
                    #pragma unroll
                    for (int e = 0; e < 4; e++)
                        acc[mi][ni][e] = 0.0f;

            #pragma unroll
            for (int ks = 0; ks < 8; ks++) {
                uint32_t a[2][4];
                #pragma unroll
                for (int mi = 0; mi < 2; mi++) {
                    int R = warpM * 32 + mi * 16 + rin + (grp & 1) * 8;
                    int C = ks * 2 + (grp >> 1);
                    LDSM_X4(a[mi][0], a[mi][1], a[mi][2], a[mi][3], aBase + sw_off(R, C));
                }
                uint32_t b[8][2];
                #pragma unroll
                for (int nb = 0; nb < 4; nb++) {
                    int R = warpN * 64 + nb * 16 + rin + (grp >> 1) * 8;
                    int C = ks * 2 + (grp & 1);
                    LDSM_X4(b[nb * 2][0], b[nb * 2][1], b[nb * 2 + 1][0], b[nb * 2 + 1][1],
                            bBase + sw_off(R, C));
                }
                #pragma unroll
                for (int mi = 0; mi < 2; mi++)
                    #pragma unroll
                    for (int ni = 0; ni < 8; ni++)
                        mma16816(acc[mi][ni], a[mi], b[ni]);
            }

            // ---- epilogue (no barriers); acc IS the base-2 exponent ----
            if (isDiag) {
                #pragma unroll
                for (int mi = 0; mi < 2; mi++) {
                    int grow0 = rowBase + warpM * 32 + mi * 16 + g;
                    int grow1 = grow0 + 8;
                    #pragma unroll
                    for (int ni = 0; ni < 8; ni++) {
                        int gc = colBase + warpN * 64 + ni * 8 + q4 * 2;
                        if (gc != grow0)     rs[mi][0] += ex2f(acc[mi][ni][0]);
                        if (gc + 1 != grow0) rs[mi][0] += ex2f(acc[mi][ni][1]);
                        if (gc != grow1)     rs[mi][1] += ex2f(acc[mi][ni][2]);
                        if (gc + 1 != grow1) rs[mi][1] += ex2f(acc[mi][ni][3]);
                    }
                }
            } else {
                float cp[8][2];
                #pragma unroll
                for (int ni = 0; ni < 8; ni++) { cp[ni][0] = 0.0f; cp[ni][1] = 0.0f; }

                #pragma unroll
                for (int mi = 0; mi < 2; mi++) {
                    int grow0 = rowBase + warpM * 32 + mi * 16 + g;
                    int grow1 = grow0 + 8;
                    #pragma unroll
                    for (int ni = 0; ni < 8; ni++) {
                        float v0 = acc[mi][ni][0];
                        float v1 = acc[mi][ni][1];
                        float v2 = acc[mi][ni][2];
                        float v3 = acc[mi][ni][3];
                        if (isPart) {
                            int gc = colBase + warpN * 64 + ni * 8 + q4 * 2;
                            int part0 = grow0 ^ BHALF;
                            int part1 = grow1 ^ BHALF;
                            if (gc == part0)     { g_pos[grow0] = v0; g_pos[part0] = v0; }
                            if (gc + 1 == part0) { g_pos[grow0] = v1; g_pos[part0] = v1; }
                            if (gc == part1)     { g_pos[grow1] = v2; g_pos[part1] = v2; }
                            if (gc + 1 == part1) { g_pos[grow1] = v3; g_pos[part1] = v3; }
                        }
                        float e0 = ex2f(v0);
                        float e1 = ex2f(v1);
                        float e2 = ex2f(v2);
                        float e3 = ex2f(v3);
                        rs[mi][0] += e0 + e1;
                        rs[mi][1] += e2 + e3;
                        cp[ni][0] += e0 + e2;
                        cp[ni][1] += e1 + e3;
                    }
                }

                // ---- column reduce-scatter over the 8 g-groups (14 shfls) ----
                #pragma unroll
                for (int k = 0; k < 4; k++)
                    #pragma unroll
                    for (int e = 0; e < 2; e++) {
                        float send = sel1 ? cp[k][e] : cp[k + 4][e];
                        float recv = __shfl_xor_sync(0xFFFFFFFFu, send, 4);
                        cp[sel1 * 4 + k][e] += recv;
                    }
                int base1 = sel1 * 4;
                #pragma unroll
                for (int k = 0; k < 2; k++)
                    #pragma unroll
                    for (int e = 0; e < 2; e++) {
                        float send = sel2 ? cp[base1 + k][e] : cp[base1 + 2 + k][e];
                        float recv = __shfl_xor_sync(0xFFFFFFFFu, send, 8);
                        cp[base1 + sel2 * 2 + k][e] += recv;
                    }
                int base2 = base1 + sel2 * 2;
                #pragma unroll
                for (int e = 0; e < 2; e++) {
                    float send = sel3 ? cp[base2][e] : cp[base2 + 1][e];
                    float recv = __shfl_xor_sync(0xFFFFFFFFu, send, 16);
                    cp[base2 + sel3][e] += recv;
                }
                int colBaseW = colBase + warpN * 64 + niOwn * 8 + q4 * 2;
                atomicAdd(&g_denom[colBaseW + 0], cp[base2 + sel3][0]);
                atomicAdd(&g_denom[colBaseW + 1], cp[base2 + sel3][1]);
            }
        }

        // flush accumulated row sums once per chunk
        #pragma unroll
        for (int mi = 0; mi < 2; mi++) {
            #pragma unroll
            for (int h = 0; h < 2; h++) {
                float v = rs[mi][h];
                v += __shfl_xor_sync(0xFFFFFFFFu, v, 1);
                v += __shfl_xor_sync(0xFFFFFFFFu, v, 2);
                if (q4 == 0)
                    atomicAdd(&g_denom[rowBase + warpM * 32 + mi * 16 + g + h * 8], v);
            }
        }
    }

    grid_barrier(&g_bar2, tid);

    // ================= phase 3: CTA 0 log-reduce =================
    if (blockIdx.x == 0) {
        float* sh = reinterpret_cast<float*>(ds);
        float s = 0.0f;
        for (int i = tid; i < ROWS_TOTAL; i += 256)
            s += __logf(g_denom[i]) - LN2 * g_pos[i];   // pos term = 10*sim
        sh[tid] = s;
        __syncthreads();
        for (int o = 128; o; o >>= 1) {
            if (tid < o) sh[tid] += sh[tid + o];
            __syncthreads();
        }
        if (tid == 0)
            out[0] = sh[0] / (float)ROWS_TOTAL;
    }
}

// ---------------- launch ----------------
extern "C" void kernel_launch(void* const* d_in, const int* in_sizes, int n_in,
                              void* d_out, int out_size)
{
    const float* xi = (const float*)d_in[0];
    const float* xj = (const float*)d_in[1];
    float* out = (float*)d_out;
    (void)in_sizes; (void)n_in; (void)out_size;

    cudaFuncSetAttribute(simclr_fused_kernel,
                         cudaFuncAttributeMaxDynamicSharedMemorySize, SMEM_TOTAL);

    simclr_fused_kernel<<<NCHUNKS, 256, SMEM_TOTAL>>>(xi, xj, out);
}